// round 4
// baseline (speedup 1.0000x reference)
#include <cuda_runtime.h>

#define BB 16
#define LTOT 128
#define LQ 32                       // L atoms per block (ZSPLIT=4)
#define PPTOT 8192
#define NTHREADS 128
#define XCHUNKS 32                  // PPTOT / (NTHREADS*2)
#define ZSPLIT 4
#define NTILES (XCHUNKS * ZSPLIT)   // 128 partial slots per batch
#define TOTBLK (XCHUNKS * BB * ZSPLIT)  // 2048

__device__ float g_part[BB][4][NTILES];
__device__ unsigned int g_cnt = 0;

typedef unsigned long long f2;

__device__ __forceinline__ float rsqrt_a(float x) { float y; asm("rsqrt.approx.f32 %0,%1;" : "=f"(y) : "f"(x)); return y; }
__device__ __forceinline__ float sqrt_a(float x)  { float y; asm("sqrt.approx.f32 %0,%1;"  : "=f"(y) : "f"(x)); return y; }
__device__ __forceinline__ float rcp_a(float x)   { float y; asm("rcp.approx.f32 %0,%1;"   : "=f"(y) : "f"(x)); return y; }
__device__ __forceinline__ float ex2_a(float x)   { float y; asm("ex2.approx.f32 %0,%1;"   : "=f"(y) : "f"(x)); return y; }

__device__ __forceinline__ f2 pk(float lo, float hi) { f2 r; asm("mov.b64 %0,{%1,%2};" : "=l"(r) : "f"(lo), "f"(hi)); return r; }
__device__ __forceinline__ void upk(f2 v, float& lo, float& hi) { asm("mov.b64 {%0,%1},%2;" : "=f"(lo), "=f"(hi) : "l"(v)); }
__device__ __forceinline__ f2 fma2(f2 a, f2 b, f2 c) { f2 r; asm("fma.rn.f32x2 %0,%1,%2,%3;" : "=l"(r) : "l"(a), "l"(b), "l"(c)); return r; }
__device__ __forceinline__ f2 mul2(f2 a, f2 b) { f2 r; asm("mul.rn.f32x2 %0,%1,%2;" : "=l"(r) : "l"(a), "l"(b)); return r; }
__device__ __forceinline__ f2 add2(f2 a, f2 b) { f2 r; asm("add.rn.f32x2 %0,%1,%2;" : "=l"(r) : "l"(a), "l"(b)); return r; }

__global__ void __launch_bounds__(NTHREADS) pair_kernel(
    const float* __restrict__ posL, const float* __restrict__ posP,
    const float* __restrict__ qL,   const float* __restrict__ qP,
    const float* __restrict__ xL,   const float* __restrict__ xP,
    const float* __restrict__ vdw,  const float* __restrict__ epst,
    float* __restrict__ out)
{
    // Ligand scalars, pre-duplicated; each row = 4 x 16B so LDS.128 yields 2 packed
    // operands per load. [l]: (x,x)(y,y)(z,z)(83q,83q)(rl,rl)(se,se)(x0,x0)(pad)
    __shared__ __align__(16) float2 sL[LQ][8];
    __shared__ float  red[4][4];
    __shared__ int    s_last;

    const int b   = blockIdx.y;
    const int tid = threadIdx.x;
    const int lbase = blockIdx.z * LQ;

    if (tid < LQ) {
        const int l = lbase + tid;
        const float* xl = xL + ((size_t)b * LTOT + l) * 9;
        float rl = 0.0f, el = 0.0f;
#pragma unroll
        for (int i = 0; i < 9; i++) {
            float v = xl[i];
            rl = fmaf(v, vdw[i],  rl);
            el = fmaf(v, epst[i], el);
        }
        el = fmaxf(el, 0.0f);
        const float* pl = posL + ((size_t)b * LTOT + l) * 3;
        float aw = 83.015f * qL[b * LTOT + l];
        float se = sqrt_a(el);
        sL[tid][0] = make_float2(pl[0], pl[0]);
        sL[tid][1] = make_float2(pl[1], pl[1]);
        sL[tid][2] = make_float2(pl[2], pl[2]);
        sL[tid][3] = make_float2(aw, aw);
        sL[tid][4] = make_float2(rl, rl);
        sL[tid][5] = make_float2(se, se);
        sL[tid][6] = make_float2(xl[0], xl[0]);
        sL[tid][7] = make_float2(0.0f, 0.0f);
    }
    __syncthreads();

    // --- per-thread protein atoms (2, packed) ---
    const int p0 = blockIdx.x * (NTHREADS * 2) + tid;
    const int p1 = p0 + NTHREADS;
    f2 npx, npy, npz, qp, rp, sep4, x0p;
    {
        const size_t b0 = (size_t)b * PPTOT + p0;
        const size_t b1 = (size_t)b * PPTOT + p1;
        const float* pp0 = posP + b0 * 3;
        const float* pp1 = posP + b1 * 3;
        npx = pk(-pp0[0], -pp1[0]);
        npy = pk(-pp0[1], -pp1[1]);
        npz = pk(-pp0[2], -pp1[2]);
        qp  = pk(qP[b0], qP[b1]);
        const float* xp0 = xP + b0 * 4;
        const float* xp1 = xP + b1 * 4;
        float r0 = fmaf(xp0[0], 1.7f, fmaf(xp0[1], 1.55f, fmaf(xp0[2], 1.52f, xp0[3] * 1.8f)));
        float r1 = fmaf(xp1[0], 1.7f, fmaf(xp1[1], 1.55f, fmaf(xp1[2], 1.52f, xp1[3] * 1.8f)));
        float e0 = fmaf(xp0[0], 0.1f, fmaf(xp0[1], 0.1f, fmaf(xp0[2], 0.15f, xp0[3] * 0.2f)));
        float e1 = fmaf(xp1[0], 0.1f, fmaf(xp1[1], 0.1f, fmaf(xp1[2], 0.15f, xp1[3] * 0.2f)));
        rp   = pk(r0, r1);
        sep4 = pk(4.0f * sqrt_a(e0), 4.0f * sqrt_a(e1));
        x0p  = pk(xp0[0], xp1[0]);
    }

    // packed constants
    const f2 C_EPS  = pk(1e-8f, 1e-8f);
    const f2 C_Z    = pk(0.005f, 0.005f);
    const f2 C_T1   = pk(-0.333333333f, -0.333333333f);
    const f2 C_T2   = pk(0.133333333f, 0.133333333f);
    const f2 C_ONE  = pk(1.0f, 1.0f);
    const f2 C_NEG1 = pk(-1.0f, -1.0f);
    const f2 C_M300 = pk(-3.3333333333e-3f, -3.3333333333e-3f);
    const f2 C_K1   = pk(2.8853900817779268f, 2.8853900817779268f);
    const f2 C_K0   = pk(-34.624680981335124f, -34.624680981335124f);
    const f2 C_256  = pk(256.0f, 256.0f);

    f2 acc_s = 0ull, acc_l = 0ull, acc_h = 0ull;
    float accp0 = 0.0f, accp1 = 0.0f;

#pragma unroll 8
    for (int l = 0; l < LQ; l++) {
        const ulonglong2* slv = (const ulonglong2*)sL[l];
        ulonglong2 v01 = slv[0];   // (x,x) (y,y)
        ulonglong2 v23 = slv[1];   // (z,z) (aw,aw)
        ulonglong2 v45 = slv[2];   // (rl,rl) (se,se)
        ulonglong2 v67 = slv[3];   // (x0,x0) pad

        f2 dx = add2(v01.x, npx);
        f2 dy = add2(v01.y, npy);
        f2 dz = add2(v23.x, npz);
        f2 d2 = fma2(dx, dx, fma2(dy, dy, fma2(dz, dz, C_EPS)));  // dist_sq + 1e-8
        f2 sig  = add2(v45.x, rp);
        f2 sig2x = add2(sig, sig);
        f2 s2   = fma2(sig, sig2x, d2);                           // + 2*sigma^2
        float s2l, s2h; upk(s2, s2l, s2h);
        f2 isd = pk(rsqrt_a(s2l), rsqrt_a(s2h));                  // 1/soft_dist

        // e_elec = 200*tanh(eer/200), |z|<=0.2 -> odd degree-5 poly
        f2 eer = mul2(mul2(v23.y, qp), isd);
        f2 z   = mul2(eer, C_Z);
        f2 w   = mul2(z, z);
        f2 p   = fma2(w, fma2(w, C_T2, C_T1), C_ONE);
        f2 ee  = mul2(eer, p);

        // LJ soft-core (always <= 0): evr = ce * r6 * (r6 - 1)
        f2 ratio = mul2(sig, isd);
        f2 r2 = mul2(ratio, ratio);
        f2 r4 = mul2(r2, r2);
        f2 r6 = mul2(r4, r2);
        f2 ce = mul2(v45.y, sep4);
        f2 r6m1 = add2(r6, C_NEG1);
        f2 evr  = mul2(mul2(ce, r6), r6m1);
        f2 e2 = mul2(evr, evr);
        f2 e3 = mul2(e2, evr);
        f2 suml = add2(ee, evr);                  // log branch: clamp is identity
        f2 sums = fma2(e3, C_M300, suml);         // tanh cubic correction

        float d2l, d2h; upk(d2, d2l, d2h);
        float dl = sqrt_a(d2l), dh = sqrt_a(d2h);
        f2 d = pk(dl, dh);

        // mask = 1/(1+ex); fused with hsa: rab = 1/((1+ex)*(d^4+256))
        f2 exarg = fma2(d, C_K1, C_K0);
        float xal, xah; upk(exarg, xal, xah);
        f2 ex = pk(ex2_a(xal), ex2_a(xah));
        f2 hd = fma2(d2, d2, C_256);              // (d2+1e-8)^2 + 256
        f2 ab = fma2(ex, hd, hd);                 // (1+ex)*hd
        float abl, abh; upk(ab, abl, abh);
        f2 rab  = pk(rcp_a(abl), rcp_a(abh));
        f2 mask = mul2(hd, rab);

        f2 wcc = mul2(v67.x, x0p);
        acc_h = fma2(wcc, rab, acc_h);            // hsa_term*mask = 256*rab (256 in epilogue)
        acc_s = fma2(sums, mask, acc_s);
        acc_l = fma2(suml, mask, acc_l);

        // pauli overlap (scalar; fmaxf -> alu pipe)
        float sgl, sgh; upk(sig, sgl, sgh);
        float ovl = fmaxf(fmaf(sgl, 0.6f, -dl), 0.0f);
        float ovh = fmaxf(fmaf(sgh, 0.6f, -dh), 0.0f);
        accp0 = fmaf(ovl, ovl, accp0);
        accp1 = fmaf(ovh, ovh, accp1);
    }

    // --- block reduction ---
    float v0l, v0h, v1l, v1h, v2l, v2h;
    upk(acc_s, v0l, v0h);
    upk(acc_l, v1l, v1h);
    upk(acc_h, v2l, v2h);
    float v0 = v0l + v0h, v1 = v1l + v1h, v2 = v2l + v2h, v3 = accp0 + accp1;
#pragma unroll
    for (int off = 16; off > 0; off >>= 1) {
        v0 += __shfl_xor_sync(0xFFFFFFFFu, v0, off);
        v1 += __shfl_xor_sync(0xFFFFFFFFu, v1, off);
        v2 += __shfl_xor_sync(0xFFFFFFFFu, v2, off);
        v3 += __shfl_xor_sync(0xFFFFFFFFu, v3, off);
    }
    const int wid = tid >> 5;
    if ((tid & 31) == 0) {
        red[wid][0] = v0; red[wid][1] = v1; red[wid][2] = v2; red[wid][3] = v3;
    }
    __syncthreads();
    const int slot = blockIdx.z * XCHUNKS + blockIdx.x;
    if (tid < 4) {
        float s = red[0][tid] + red[1][tid] + red[2][tid] + red[3][tid];
        g_part[b][tid][slot] = s;
    }
    __threadfence();
    if (tid == 0) {
        unsigned int old = atomicAdd(&g_cnt, 1u);
        s_last = (old == TOTBLK - 1) ? 1 : 0;
    }
    __syncthreads();
    if (!s_last) return;

    // --- last block: final reduction + epilogue ---
    __threadfence();
    __shared__ float fin[BB][4];
    {
        // 128 threads: 2 threads per (batch,comp) slot, each sums half the tiles
        const int slot2 = tid >> 1;           // 0..63
        const int half  = tid & 1;
        const int fb = slot2 >> 2, fc = slot2 & 3;
        float s = 0.0f;
#pragma unroll 16
        for (int i = half * (NTILES / 2); i < (half + 1) * (NTILES / 2); i++)
            s += g_part[fb][fc][i];
        s += __shfl_xor_sync(0xFFFFFFFFu, s, 1);
        if (half == 0) fin[fb][fc] = s;
    }
    __syncthreads();
    if (tid < BB) {
        float s  = fin[tid][0];
        float lg = fin[tid][1];
        float h  = fin[tid][2];
        float pa = fin[tid][3];

        float e_hsa   = -0.5f * 256.0f * h;
        float e_pauli = 95.257412682243336f * pa;   // sigmoid(3.0)*100

        float e_raw  = s + 5.0f * e_hsa + e_pauli;
        float e_hard = fminf(e_pauli, 10000.0f);
        float e_soft_log = fminf(fmaxf(lg + 5.0f * e_hsa, -500.0f), 5000.0f);
        float loge = fminf(e_soft_log + e_hard, 1000000.0f);

        out[tid]      = e_raw;
        out[16 + tid] = e_hard;
        out[33 + tid] = loge;
    }
    if (tid == 0) {
        out[32] = 2.0f;   // ALPHA
        g_cnt = 0;        // reset for next graph replay (deterministic)
    }
}

extern "C" void kernel_launch(void* const* d_in, const int* in_sizes, int n_in,
                              void* d_out, int out_size) {
    const float* posL = (const float*)d_in[0];
    const float* posP = (const float*)d_in[1];
    const float* qL   = (const float*)d_in[2];
    const float* qP   = (const float*)d_in[3];
    const float* xL   = (const float*)d_in[4];
    const float* xP   = (const float*)d_in[5];
    const float* vdw  = (const float*)d_in[6];
    const float* epst = (const float*)d_in[7];
    float* out = (float*)d_out;

    dim3 grid(XCHUNKS, BB, ZSPLIT);
    pair_kernel<<<grid, NTHREADS>>>(posL, posP, qL, qP, xL, xP, vdw, epst, out);
}

// round 5
// speedup vs baseline: 1.0062x; 1.0062x over previous
#include <cuda_runtime.h>

#define BB 16
#define LTOT 128
#define LQ 32                       // L atoms per block (ZSPLIT=4)
#define PPTOT 8192
#define NTHREADS 128
#define XCHUNKS 32                  // PPTOT / (NTHREADS*2)
#define ZSPLIT 4
#define NTILES (XCHUNKS * ZSPLIT)   // 128 partial slots per batch
#define TOTBLK (XCHUNKS * BB * ZSPLIT)  // 2048

__device__ float g_part[BB][4][NTILES];
__device__ unsigned int g_cnt = 0;

typedef unsigned long long f2;

__device__ __forceinline__ float rsqrt_a(float x) { float y; asm("rsqrt.approx.f32 %0,%1;" : "=f"(y) : "f"(x)); return y; }
__device__ __forceinline__ float sqrt_a(float x)  { float y; asm("sqrt.approx.f32 %0,%1;"  : "=f"(y) : "f"(x)); return y; }
__device__ __forceinline__ float rcp_a(float x)   { float y; asm("rcp.approx.f32 %0,%1;"   : "=f"(y) : "f"(x)); return y; }
__device__ __forceinline__ float ex2_a(float x)   { float y; asm("ex2.approx.f32 %0,%1;"   : "=f"(y) : "f"(x)); return y; }

__device__ __forceinline__ f2 pk(float lo, float hi) { f2 r; asm("mov.b64 %0,{%1,%2};" : "=l"(r) : "f"(lo), "f"(hi)); return r; }
__device__ __forceinline__ void upk(f2 v, float& lo, float& hi) { asm("mov.b64 {%0,%1},%2;" : "=f"(lo), "=f"(hi) : "l"(v)); }
__device__ __forceinline__ f2 fma2(f2 a, f2 b, f2 c) { f2 r; asm("fma.rn.f32x2 %0,%1,%2,%3;" : "=l"(r) : "l"(a), "l"(b), "l"(c)); return r; }
__device__ __forceinline__ f2 mul2(f2 a, f2 b) { f2 r; asm("mul.rn.f32x2 %0,%1,%2;" : "=l"(r) : "l"(a), "l"(b)); return r; }
__device__ __forceinline__ f2 add2(f2 a, f2 b) { f2 r; asm("add.rn.f32x2 %0,%1,%2;" : "=l"(r) : "l"(a), "l"(b)); return r; }

__global__ void __launch_bounds__(NTHREADS) pair_kernel(
    const float* __restrict__ posL, const float* __restrict__ posP,
    const float* __restrict__ qL,   const float* __restrict__ qP,
    const float* __restrict__ xL,   const float* __restrict__ xP,
    const float* __restrict__ vdw,  const float* __restrict__ epst,
    float* __restrict__ out)
{
    // Ligand scalars, pre-duplicated; each row = 4 x 16B so LDS.128 yields 2 packed
    // operands per load. [l]: (x,x)(y,y)(z,z)(83q,83q)(rl,rl)(se,se)(x0,x0)(pad)
    __shared__ __align__(16) float2 sL[LQ][8];
    __shared__ float  red[4][4];
    __shared__ int    s_last;

    const int b   = blockIdx.y;
    const int tid = threadIdx.x;
    const int lbase = blockIdx.z * LQ;

    if (tid < LQ) {
        const int l = lbase + tid;
        const float* xl = xL + ((size_t)b * LTOT + l) * 9;
        float rl = 0.0f, el = 0.0f;
#pragma unroll
        for (int i = 0; i < 9; i++) {
            float v = xl[i];
            rl = fmaf(v, vdw[i],  rl);
            el = fmaf(v, epst[i], el);
        }
        el = fmaxf(el, 0.0f);
        const float* pl = posL + ((size_t)b * LTOT + l) * 3;
        float aw = 83.015f * qL[b * LTOT + l];
        float se = sqrt_a(el);
        sL[tid][0] = make_float2(pl[0], pl[0]);
        sL[tid][1] = make_float2(pl[1], pl[1]);
        sL[tid][2] = make_float2(pl[2], pl[2]);
        sL[tid][3] = make_float2(aw, aw);
        sL[tid][4] = make_float2(rl, rl);
        sL[tid][5] = make_float2(se, se);
        sL[tid][6] = make_float2(xl[0], xl[0]);
        sL[tid][7] = make_float2(0.0f, 0.0f);
    }
    __syncthreads();

    // --- per-thread protein atoms (2, packed) ---
    const int p0 = blockIdx.x * (NTHREADS * 2) + tid;
    const int p1 = p0 + NTHREADS;
    f2 npx, npy, npz, qp, rp, sep4, x0p;
    {
        const size_t b0 = (size_t)b * PPTOT + p0;
        const size_t b1 = (size_t)b * PPTOT + p1;
        const float* pp0 = posP + b0 * 3;
        const float* pp1 = posP + b1 * 3;
        npx = pk(-pp0[0], -pp1[0]);
        npy = pk(-pp0[1], -pp1[1]);
        npz = pk(-pp0[2], -pp1[2]);
        qp  = pk(qP[b0], qP[b1]);
        const float* xp0 = xP + b0 * 4;
        const float* xp1 = xP + b1 * 4;
        float r0 = fmaf(xp0[0], 1.7f, fmaf(xp0[1], 1.55f, fmaf(xp0[2], 1.52f, xp0[3] * 1.8f)));
        float r1 = fmaf(xp1[0], 1.7f, fmaf(xp1[1], 1.55f, fmaf(xp1[2], 1.52f, xp1[3] * 1.8f)));
        float e0 = fmaf(xp0[0], 0.1f, fmaf(xp0[1], 0.1f, fmaf(xp0[2], 0.15f, xp0[3] * 0.2f)));
        float e1 = fmaf(xp1[0], 0.1f, fmaf(xp1[1], 0.1f, fmaf(xp1[2], 0.15f, xp1[3] * 0.2f)));
        rp   = pk(r0, r1);
        sep4 = pk(4.0f * sqrt_a(e0), 4.0f * sqrt_a(e1));
        x0p  = pk(xp0[0], xp1[0]);
    }

    // packed constants (tanh poly in u = eer^2: p = 1 + u*(-8.3333333e-6 + u*8.3333333e-11))
    const f2 C_EPS  = pk(1e-8f, 1e-8f);
    const f2 C_U1   = pk(-8.3333333e-6f, -8.3333333e-6f);
    const f2 C_U2   = pk(8.3333333e-11f, 8.3333333e-11f);
    const f2 C_ONE  = pk(1.0f, 1.0f);
    const f2 C_NEG1 = pk(-1.0f, -1.0f);
    const f2 C_M300 = pk(-3.3333333333e-3f, -3.3333333333e-3f);
    const f2 C_K1   = pk(2.8853900817779268f, 2.8853900817779268f);
    const f2 C_K0   = pk(-34.624680981335124f, -34.624680981335124f);
    const f2 C_256  = pk(256.0f, 256.0f);

    f2 acc_s = 0ull, acc_l = 0ull, acc_h = 0ull;
    float accp0 = 0.0f, accp1 = 0.0f;

    // --- main loop: 2 ligand atoms per iteration, stages interleaved for ILP ---
#pragma unroll 4
    for (int t = 0; t < LQ / 2; t++) {
        const ulonglong2* sa = (const ulonglong2*)sL[2 * t];
        const ulonglong2* sb = (const ulonglong2*)sL[2 * t + 1];
        ulonglong2 a01 = sa[0], a23 = sa[1], a45 = sa[2], a67 = sa[3];
        ulonglong2 b01 = sb[0], b23 = sb[1], b45 = sb[2], b67 = sb[3];

        // ---- stage A: distances (both) ----
        f2 dxa = add2(a01.x, npx), dya = add2(a01.y, npy), dza = add2(a23.x, npz);
        f2 dxb = add2(b01.x, npx), dyb = add2(b01.y, npy), dzb = add2(b23.x, npz);
        f2 d2a = fma2(dxa, dxa, fma2(dya, dya, fma2(dza, dza, C_EPS)));
        f2 d2b = fma2(dxb, dxb, fma2(dyb, dyb, fma2(dzb, dzb, C_EPS)));
        f2 siga = add2(a45.x, rp);
        f2 sigb = add2(b45.x, rp);
        f2 s2a = fma2(siga, add2(siga, siga), d2a);
        f2 s2b = fma2(sigb, add2(sigb, sigb), d2b);

        // ---- MUFU batch 1: rsqrt(soft) x4, sqrt(dist) x4 ----
        float s2al, s2ah, s2bl, s2bh, d2al, d2ah, d2bl, d2bh;
        upk(s2a, s2al, s2ah); upk(s2b, s2bl, s2bh);
        upk(d2a, d2al, d2ah); upk(d2b, d2bl, d2bh);
        f2 isda = pk(rsqrt_a(s2al), rsqrt_a(s2ah));
        f2 isdb = pk(rsqrt_a(s2bl), rsqrt_a(s2bh));
        float dal = sqrt_a(d2al), dah = sqrt_a(d2ah);
        float dbl = sqrt_a(d2bl), dbh = sqrt_a(d2bh);
        f2 da = pk(dal, dah);
        f2 db = pk(dbl, dbh);

        // ---- stage B: elec + LJ (both) ----
        f2 eera = mul2(mul2(a23.y, qp), isda);
        f2 eerb = mul2(mul2(b23.y, qp), isdb);
        f2 ua = mul2(eera, eera);
        f2 ub = mul2(eerb, eerb);
        f2 pa = fma2(ua, fma2(ua, C_U2, C_U1), C_ONE);
        f2 pb = fma2(ub, fma2(ub, C_U2, C_U1), C_ONE);
        f2 eea = mul2(eera, pa);
        f2 eeb = mul2(eerb, pb);

        f2 rata = mul2(siga, isda);
        f2 ratb = mul2(sigb, isdb);
        f2 r2a = mul2(rata, rata), r2b = mul2(ratb, ratb);
        f2 r6a = mul2(mul2(r2a, r2a), r2a);
        f2 r6b = mul2(mul2(r2b, r2b), r2b);
        f2 cea = mul2(a45.y, sep4);
        f2 ceb = mul2(b45.y, sep4);
        f2 evra = mul2(mul2(cea, r6a), add2(r6a, C_NEG1));
        f2 evrb = mul2(mul2(ceb, r6b), add2(r6b, C_NEG1));
        f2 sumla = add2(eea, evra);                          // log branch (clamp = identity)
        f2 sumlb = add2(eeb, evrb);
        f2 sumsa = fma2(mul2(mul2(evra, evra), evra), C_M300, sumla);
        f2 sumsb = fma2(mul2(mul2(evrb, evrb), evrb), C_M300, sumlb);

        // ---- stage C: mask (+fused hsa reciprocal), both ----
        f2 xga = fma2(da, C_K1, C_K0);
        f2 xgb = fma2(db, C_K1, C_K0);
        float xal, xah, xbl, xbh;
        upk(xga, xal, xah); upk(xgb, xbl, xbh);
        f2 exa = pk(ex2_a(xal), ex2_a(xah));
        f2 exb = pk(ex2_a(xbl), ex2_a(xbh));
        f2 hda = fma2(d2a, d2a, C_256);
        f2 hdb = fma2(d2b, d2b, C_256);
        f2 aba = fma2(exa, hda, hda);
        f2 abb = fma2(exb, hdb, hdb);
        float abal, abah, abbl, abbh;
        upk(aba, abal, abah); upk(abb, abbl, abbh);
        f2 raba = pk(rcp_a(abal), rcp_a(abah));
        f2 rabb = pk(rcp_a(abbl), rcp_a(abbh));
        f2 mka = mul2(hda, raba);
        f2 mkb = mul2(hdb, rabb);

        // ---- accumulate ----
        acc_h = fma2(a67.x, raba, acc_h);      // x0p factored out post-loop
        acc_h = fma2(b67.x, rabb, acc_h);
        acc_s = fma2(sumsa, mka, acc_s);
        acc_s = fma2(sumsb, mkb, acc_s);
        acc_l = fma2(sumla, mka, acc_l);
        acc_l = fma2(sumlb, mkb, acc_l);

        // ---- pauli (scalar; FMNMX on alu pipe) ----
        float sal, sah, sbl_, sbh_;
        upk(siga, sal, sah); upk(sigb, sbl_, sbh_);
        float ov0 = fmaxf(fmaf(sal, 0.6f, -dal), 0.0f);
        float ov1 = fmaxf(fmaf(sah, 0.6f, -dah), 0.0f);
        float ov2 = fmaxf(fmaf(sbl_, 0.6f, -dbl), 0.0f);
        float ov3 = fmaxf(fmaf(sbh_, 0.6f, -dbh), 0.0f);
        accp0 = fmaf(ov0, ov0, accp0);
        accp1 = fmaf(ov1, ov1, accp1);
        accp0 = fmaf(ov2, ov2, accp0);
        accp1 = fmaf(ov3, ov3, accp1);
    }

    acc_h = mul2(acc_h, x0p);   // deferred x_P[0] factor

    // --- block reduction ---
    float v0l, v0h, v1l, v1h, v2l, v2h;
    upk(acc_s, v0l, v0h);
    upk(acc_l, v1l, v1h);
    upk(acc_h, v2l, v2h);
    float v0 = v0l + v0h, v1 = v1l + v1h, v2 = v2l + v2h, v3 = accp0 + accp1;
#pragma unroll
    for (int off = 16; off > 0; off >>= 1) {
        v0 += __shfl_xor_sync(0xFFFFFFFFu, v0, off);
        v1 += __shfl_xor_sync(0xFFFFFFFFu, v1, off);
        v2 += __shfl_xor_sync(0xFFFFFFFFu, v2, off);
        v3 += __shfl_xor_sync(0xFFFFFFFFu, v3, off);
    }
    const int wid = tid >> 5;
    if ((tid & 31) == 0) {
        red[wid][0] = v0; red[wid][1] = v1; red[wid][2] = v2; red[wid][3] = v3;
    }
    __syncthreads();
    const int slot = blockIdx.z * XCHUNKS + blockIdx.x;
    if (tid < 4) {
        float s = red[0][tid] + red[1][tid] + red[2][tid] + red[3][tid];
        g_part[b][tid][slot] = s;
    }
    __threadfence();
    if (tid == 0) {
        unsigned int old = atomicAdd(&g_cnt, 1u);
        s_last = (old == TOTBLK - 1) ? 1 : 0;
    }
    __syncthreads();
    if (!s_last) return;

    // --- last block: final reduction + epilogue ---
    __threadfence();
    __shared__ float fin[BB][4];
    {
        const int slot2 = tid >> 1;           // 0..63
        const int half  = tid & 1;
        const int fb = slot2 >> 2, fc = slot2 & 3;
        float s = 0.0f;
#pragma unroll 16
        for (int i = half * (NTILES / 2); i < (half + 1) * (NTILES / 2); i++)
            s += g_part[fb][fc][i];
        s += __shfl_xor_sync(0xFFFFFFFFu, s, 1);
        if (half == 0) fin[fb][fc] = s;
    }
    __syncthreads();
    if (tid < BB) {
        float s  = fin[tid][0];
        float lg = fin[tid][1];
        float h  = fin[tid][2];
        float pa = fin[tid][3];

        float e_hsa   = -0.5f * 256.0f * h;
        float e_pauli = 95.257412682243336f * pa;   // sigmoid(3.0)*100

        float e_raw  = s + 5.0f * e_hsa + e_pauli;
        float e_hard = fminf(e_pauli, 10000.0f);
        float e_soft_log = fminf(fmaxf(lg + 5.0f * e_hsa, -500.0f), 5000.0f);
        float loge = fminf(e_soft_log + e_hard, 1000000.0f);

        out[tid]      = e_raw;
        out[16 + tid] = e_hard;
        out[33 + tid] = loge;
    }
    if (tid == 0) {
        out[32] = 2.0f;   // ALPHA
        g_cnt = 0;        // reset for next graph replay (deterministic)
    }
}

extern "C" void kernel_launch(void* const* d_in, const int* in_sizes, int n_in,
                              void* d_out, int out_size) {
    const float* posL = (const float*)d_in[0];
    const float* posP = (const float*)d_in[1];
    const float* qL   = (const float*)d_in[2];
    const float* qP   = (const float*)d_in[3];
    const float* xL   = (const float*)d_in[4];
    const float* xP   = (const float*)d_in[5];
    const float* vdw  = (const float*)d_in[6];
    const float* epst = (const float*)d_in[7];
    float* out = (float*)d_out;

    dim3 grid(XCHUNKS, BB, ZSPLIT);
    pair_kernel<<<grid, NTHREADS>>>(posL, posP, qL, qP, xL, xP, vdw, epst, out);
}

// round 6
// speedup vs baseline: 1.0525x; 1.0460x over previous
#include <cuda_runtime.h>

#define BB 16
#define LTOT 128
#define LQ 32                       // L atoms per block
#define PPTOT 8192
#define NTHREADS 128
#define XCHUNKS 16                  // PPTOT / (NTHREADS*4)
#define ZSPLIT 4
#define NTILES (XCHUNKS * ZSPLIT)   // 64 partial slots per batch
#define TOTBLK (XCHUNKS * BB * ZSPLIT)  // 1024 blocks = 1 wave @ 7 blocks/SM

__device__ float g_part[BB][4][NTILES];
__device__ unsigned int g_cnt = 0;

typedef unsigned long long f2;

__device__ __forceinline__ float rsqrt_a(float x) { float y; asm("rsqrt.approx.f32 %0,%1;" : "=f"(y) : "f"(x)); return y; }
__device__ __forceinline__ float sqrt_a(float x)  { float y; asm("sqrt.approx.f32 %0,%1;"  : "=f"(y) : "f"(x)); return y; }
__device__ __forceinline__ float rcp_a(float x)   { float y; asm("rcp.approx.f32 %0,%1;"   : "=f"(y) : "f"(x)); return y; }
__device__ __forceinline__ float ex2_a(float x)   { float y; asm("ex2.approx.f32 %0,%1;"   : "=f"(y) : "f"(x)); return y; }

__device__ __forceinline__ f2 pk(float lo, float hi) { f2 r; asm("mov.b64 %0,{%1,%2};" : "=l"(r) : "f"(lo), "f"(hi)); return r; }
__device__ __forceinline__ void upk(f2 v, float& lo, float& hi) { asm("mov.b64 {%0,%1},%2;" : "=f"(lo), "=f"(hi) : "l"(v)); }
__device__ __forceinline__ f2 fma2(f2 a, f2 b, f2 c) { f2 r; asm("fma.rn.f32x2 %0,%1,%2,%3;" : "=l"(r) : "l"(a), "l"(b), "l"(c)); return r; }
__device__ __forceinline__ f2 mul2(f2 a, f2 b) { f2 r; asm("mul.rn.f32x2 %0,%1,%2;" : "=l"(r) : "l"(a), "l"(b)); return r; }
__device__ __forceinline__ f2 add2(f2 a, f2 b) { f2 r; asm("add.rn.f32x2 %0,%1,%2;" : "=l"(r) : "l"(a), "l"(b)); return r; }

__global__ void __launch_bounds__(NTHREADS, 7) pair_kernel(
    const float* __restrict__ posL, const float* __restrict__ posP,
    const float* __restrict__ qL,   const float* __restrict__ qP,
    const float* __restrict__ xL,   const float* __restrict__ xP,
    const float* __restrict__ vdw,  const float* __restrict__ epst,
    float* __restrict__ out)
{
    // Ligand scalars, pre-duplicated; each row = 4 x 16B so LDS.128 yields 2 packed
    // operands per load. [l]: (x,x)(y,y)(z,z)(83q,83q)(rl,rl)(se,se)(x0,x0)(pad)
    __shared__ __align__(16) float2 sL[LQ][8];
    __shared__ float  red[4][4];
    __shared__ int    s_last;

    const int b   = blockIdx.y;
    const int tid = threadIdx.x;
    const int lbase = blockIdx.z * LQ;

    if (tid < LQ) {
        const int l = lbase + tid;
        const float* xl = xL + ((size_t)b * LTOT + l) * 9;
        float rl = 0.0f, el = 0.0f;
#pragma unroll
        for (int i = 0; i < 9; i++) {
            float v = xl[i];
            rl = fmaf(v, vdw[i],  rl);
            el = fmaf(v, epst[i], el);
        }
        el = fmaxf(el, 0.0f);
        const float* pl = posL + ((size_t)b * LTOT + l) * 3;
        float aw = 83.015f * qL[b * LTOT + l];
        float se = sqrt_a(el);
        sL[tid][0] = make_float2(pl[0], pl[0]);
        sL[tid][1] = make_float2(pl[1], pl[1]);
        sL[tid][2] = make_float2(pl[2], pl[2]);
        sL[tid][3] = make_float2(aw, aw);
        sL[tid][4] = make_float2(rl, rl);
        sL[tid][5] = make_float2(se, se);
        sL[tid][6] = make_float2(xl[0], xl[0]);
        sL[tid][7] = make_float2(0.0f, 0.0f);
    }
    __syncthreads();

    // --- per-thread protein atoms: 4, as two packed sets ---
    f2 npx[2], npy[2], npz[2], qp2[2], rp2[2], sep4[2], x0p2[2];
#pragma unroll
    for (int s = 0; s < 2; s++) {
        const int p0 = blockIdx.x * (NTHREADS * 4) + s * (NTHREADS * 2) + tid;
        const int p1 = p0 + NTHREADS;
        const size_t b0 = (size_t)b * PPTOT + p0;
        const size_t b1 = (size_t)b * PPTOT + p1;
        const float* pp0 = posP + b0 * 3;
        const float* pp1 = posP + b1 * 3;
        npx[s] = pk(-pp0[0], -pp1[0]);
        npy[s] = pk(-pp0[1], -pp1[1]);
        npz[s] = pk(-pp0[2], -pp1[2]);
        qp2[s] = pk(qP[b0], qP[b1]);
        const float* xp0 = xP + b0 * 4;
        const float* xp1 = xP + b1 * 4;
        float r0 = fmaf(xp0[0], 1.7f, fmaf(xp0[1], 1.55f, fmaf(xp0[2], 1.52f, xp0[3] * 1.8f)));
        float r1 = fmaf(xp1[0], 1.7f, fmaf(xp1[1], 1.55f, fmaf(xp1[2], 1.52f, xp1[3] * 1.8f)));
        float e0 = fmaf(xp0[0], 0.1f, fmaf(xp0[1], 0.1f, fmaf(xp0[2], 0.15f, xp0[3] * 0.2f)));
        float e1 = fmaf(xp1[0], 0.1f, fmaf(xp1[1], 0.1f, fmaf(xp1[2], 0.15f, xp1[3] * 0.2f)));
        rp2[s]  = pk(r0, r1);
        sep4[s] = pk(4.0f * sqrt_a(e0), 4.0f * sqrt_a(e1));
        x0p2[s] = pk(xp0[0], xp1[0]);
    }

    // packed constants (tanh poly in u = eer^2, C_ONE folded away:
    // ee = eer + (eer*u)*(C_U1 + C_U2*u))
    const f2 C_EPS  = pk(1e-8f, 1e-8f);
    const f2 C_U1   = pk(-8.3333333e-6f, -8.3333333e-6f);
    const f2 C_U2   = pk(8.3333333e-11f, 8.3333333e-11f);
    const f2 C_NEG1 = pk(-1.0f, -1.0f);
    const f2 C_K1   = pk(2.8853900817779268f, 2.8853900817779268f);
    const f2 C_K0   = pk(-34.624680981335124f, -34.624680981335124f);
    const f2 C_256  = pk(256.0f, 256.0f);

    f2 acc_l = 0ull, acc_d = 0ull;
    f2 acc_h[2] = {0ull, 0ull};
    float accp0 = 0.0f, accp1 = 0.0f;

#pragma unroll 8
    for (int l = 0; l < LQ; l++) {
        const ulonglong2* slv = (const ulonglong2*)sL[l];
        ulonglong2 v01 = slv[0];   // (x,x) (y,y)
        ulonglong2 v23 = slv[1];   // (z,z) (aw,aw)
        ulonglong2 v45 = slv[2];   // (rl,rl) (se,se)
        ulonglong2 v67 = slv[3];   // (x0,x0) pad

#pragma unroll
        for (int s = 0; s < 2; s++) {
            f2 dx = add2(v01.x, npx[s]);
            f2 dy = add2(v01.y, npy[s]);
            f2 dz = add2(v23.x, npz[s]);
            f2 d2 = fma2(dx, dx, fma2(dy, dy, fma2(dz, dz, C_EPS)));
            f2 sig  = add2(v45.x, rp2[s]);
            f2 s2   = fma2(sig, add2(sig, sig), d2);
            float s2l, s2h; upk(s2, s2l, s2h);
            f2 isd = pk(rsqrt_a(s2l), rsqrt_a(s2h));               // 1/soft_dist

            // e_elec = 200*tanh(eer/200): ee = eer + (eer*u)*(c1 + c2*u), u=eer^2
            f2 eer = mul2(mul2(v23.y, qp2[s]), isd);
            f2 u   = mul2(eer, eer);
            f2 m   = mul2(eer, u);
            f2 t   = fma2(u, C_U2, C_U1);
            f2 ee  = fma2(m, t, eer);

            // LJ soft-core (always <= 0): evr = ce * r6 * (r6 - 1)
            f2 rat = mul2(sig, isd);
            f2 r2 = mul2(rat, rat);
            f2 r6 = mul2(mul2(r2, r2), r2);
            f2 ce = mul2(v45.y, sep4[s]);
            f2 evr = mul2(mul2(ce, r6), add2(r6, C_NEG1));
            f2 e3  = mul2(mul2(evr, evr), evr);
            f2 suml = add2(ee, evr);                   // log branch (clamp = identity)

            float d2l, d2h; upk(d2, d2l, d2h);
            float dl = sqrt_a(d2l), dh = sqrt_a(d2h);

            // mask fused with hsa reciprocal: rab = 1/((1+ex)*(d^4+256))
            f2 xg = fma2(pk(dl, dh), C_K1, C_K0);
            float xal, xah; upk(xg, xal, xah);
            f2 ex = pk(ex2_a(xal), ex2_a(xah));
            f2 hd = fma2(d2, d2, C_256);
            f2 ab = fma2(ex, hd, hd);
            float abl, abh; upk(ab, abl, abh);
            f2 rab  = pk(rcp_a(abl), rcp_a(abh));
            f2 mk = mul2(hd, rab);

            acc_h[s] = fma2(v67.x, rab, acc_h[s]);     // x0p factored out post-loop
            acc_l = fma2(suml, mk, acc_l);
            acc_d = fma2(e3, mk, acc_d);               // soft = log - acc_d/300

            // pauli (scalar; FMNMX on alu pipe)
            float sgl, sgh; upk(sig, sgl, sgh);
            float ov0 = fmaxf(fmaf(sgl, 0.6f, -dl), 0.0f);
            float ov1 = fmaxf(fmaf(sgh, 0.6f, -dh), 0.0f);
            accp0 = fmaf(ov0, ov0, accp0);
            accp1 = fmaf(ov1, ov1, accp1);
        }
    }

    acc_h[0] = mul2(acc_h[0], x0p2[0]);   // deferred x_P[0] factors
    acc_h[1] = mul2(acc_h[1], x0p2[1]);

    // --- block reduction ---
    float v1l, v1h, vdl, vdh, h0l, h0h, h1l, h1h;
    upk(acc_l, v1l, v1h);
    upk(acc_d, vdl, vdh);
    upk(acc_h[0], h0l, h0h);
    upk(acc_h[1], h1l, h1h);
    float v1 = v1l + v1h;
    float v0 = fmaf(vdl + vdh, -3.3333333333e-3f, v1);   // soft sum
    float v2 = (h0l + h0h) + (h1l + h1h);
    float v3 = accp0 + accp1;
#pragma unroll
    for (int off = 16; off > 0; off >>= 1) {
        v0 += __shfl_xor_sync(0xFFFFFFFFu, v0, off);
        v1 += __shfl_xor_sync(0xFFFFFFFFu, v1, off);
        v2 += __shfl_xor_sync(0xFFFFFFFFu, v2, off);
        v3 += __shfl_xor_sync(0xFFFFFFFFu, v3, off);
    }
    const int wid = tid >> 5;
    if ((tid & 31) == 0) {
        red[wid][0] = v0; red[wid][1] = v1; red[wid][2] = v2; red[wid][3] = v3;
    }
    __syncthreads();
    const int slot = blockIdx.z * XCHUNKS + blockIdx.x;
    if (tid < 4) {
        float s = red[0][tid] + red[1][tid] + red[2][tid] + red[3][tid];
        g_part[b][tid][slot] = s;
    }
    __threadfence();
    if (tid == 0) {
        unsigned int old = atomicAdd(&g_cnt, 1u);
        s_last = (old == TOTBLK - 1) ? 1 : 0;
    }
    __syncthreads();
    if (!s_last) return;

    // --- last block: final reduction + epilogue ---
    __threadfence();
    __shared__ float fin[BB][4];
    {
        const int slot2 = tid >> 1;           // 0..63  (16 batches x 4 comps)
        const int half  = tid & 1;
        const int fb = slot2 >> 2, fc = slot2 & 3;
        float s = 0.0f;
#pragma unroll 8
        for (int i = half * (NTILES / 2); i < (half + 1) * (NTILES / 2); i++)
            s += g_part[fb][fc][i];
        s += __shfl_xor_sync(0xFFFFFFFFu, s, 1);
        if (half == 0) fin[fb][fc] = s;
    }
    __syncthreads();
    if (tid < BB) {
        float s  = fin[tid][0];
        float lg = fin[tid][1];
        float h  = fin[tid][2];
        float pa = fin[tid][3];

        float e_hsa   = -0.5f * 256.0f * h;
        float e_pauli = 95.257412682243336f * pa;   // sigmoid(3.0)*100

        float e_raw  = s + 5.0f * e_hsa + e_pauli;
        float e_hard = fminf(e_pauli, 10000.0f);
        float e_soft_log = fminf(fmaxf(lg + 5.0f * e_hsa, -500.0f), 5000.0f);
        float loge = fminf(e_soft_log + e_hard, 1000000.0f);

        out[tid]      = e_raw;
        out[16 + tid] = e_hard;
        out[33 + tid] = loge;
    }
    if (tid == 0) {
        out[32] = 2.0f;   // ALPHA
        g_cnt = 0;        // reset for next graph replay (deterministic)
    }
}

extern "C" void kernel_launch(void* const* d_in, const int* in_sizes, int n_in,
                              void* d_out, int out_size) {
    const float* posL = (const float*)d_in[0];
    const float* posP = (const float*)d_in[1];
    const float* qL   = (const float*)d_in[2];
    const float* qP   = (const float*)d_in[3];
    const float* xL   = (const float*)d_in[4];
    const float* xP   = (const float*)d_in[5];
    const float* vdw  = (const float*)d_in[6];
    const float* epst = (const float*)d_in[7];
    float* out = (float*)d_out;

    dim3 grid(XCHUNKS, BB, ZSPLIT);
    pair_kernel<<<grid, NTHREADS>>>(posL, posP, qL, qP, xL, xP, vdw, epst, out);
}